// round 16
// baseline (speedup 1.0000x reference)
#include <cuda_runtime.h>
#include <cuda_fp16.h>
#include <math.h>
#include <stdint.h>

// StableMoEGate v11: fp16 m16n8k16, 2-way split (3 passes), occupancy push:
// MT=32 -> grid 512, 4 K-groups x 2 token-halves, chunk 16k, 2-stage cp.async,
// 3 CTAs/SM (__launch_bounds__(256,3)).
// logits = x @ W^T (T=16384, H=4096, E=64); softmax; top-2; renorm softmax.
// Output: single f32 buffer [2T scores][2T idx-as-float][1 aux=0].

#define Hdim 4096
#define Edim 64
#define MT   32
#define NCHUNK 64               // 16-k steps per K-group (1024/16)
#define A_STRIDE 80             // 16 floats + 16B pad
#define A_BYTES  10240          // 128 rows (4g x 32 tok) * 80
#define B_BYTES  16384          // 4g x 2spl x 64n x 32B
#define BUFB     (A_BYTES + B_BYTES)   // 26624
#define SMEM_BYTES (2 * BUFB)          // 53248

// W pre-split to fp16 hi/lo: [spl][kstep:256][n:64][quad:4][half16:2][bit:2]
__device__ __half g_wsplit[2 * 64 * 4096];

static __device__ __forceinline__ uint32_t smem_u32(const void* p) {
    uint32_t a;
    asm("{ .reg .u64 t; cvta.to.shared.u64 t, %1; cvt.u32.u64 %0, t; }" : "=r"(a) : "l"(p));
    return a;
}
static __device__ __forceinline__ uint32_t h2u(__half2 h) {
    return *reinterpret_cast<uint32_t*>(&h);
}

__global__ void __launch_bounds__(256) split_w_kernel(const float* __restrict__ W) {
    const int i = blockIdx.x * 256 + threadIdx.x;
    if (i < 64 * 4096) {
        const int n = i >> 12, k = i & 4095;
        const float w = W[(size_t)n * 4096 + k];
        const __half hi = __float2half_rn(w);
        const __half lo = __float2half_rn(w - __half2float(hi));
        const int kin = k & 15;
        const int half = kin >> 3, quad = (kin & 7) >> 1, bit = kin & 1;
        const int idx = ((k >> 4) * 64 + n) * 16 + quad * 4 + half * 2 + bit;
        g_wsplit[idx]          = hi;
        g_wsplit[262144 + idx] = lo;
    }
}

#define MMAH(d, a0, a1, a2, a3, b0, b1)                                          \
    asm("mma.sync.aligned.m16n8k16.row.col.f32.f16.f16.f32 "                     \
        "{%0,%1,%2,%3}, {%4,%5,%6,%7}, {%8,%9}, {%0,%1,%2,%3};"                  \
        : "+f"(d[0]), "+f"(d[1]), "+f"(d[2]), "+f"(d[3])                         \
        : "r"(a0), "r"(a1), "r"(a2), "r"(a3), "r"(b0), "r"(b1))

__global__ void __launch_bounds__(256, 3) moe_gate_v11_kernel(
    const float* __restrict__ x,
    float* __restrict__ out,
    int T)
{
    extern __shared__ float smem[];
    const uint32_t sbase = smem_u32(smem);

    const int tid  = threadIdx.x;
    const int lid  = tid & 31;
    const int wid  = tid >> 5;
    const int g    = wid >> 1;            // K-group 0..3 : k in [g*1024, +1024)
    const int th   = wid & 1;             // token half: rows th*16..th*16+15
    const int gid  = lid >> 2;            // 0..7
    const int tid4 = lid & 3;             // 0..3
    const int m0   = blockIdx.x * MT;

    // ---- loader precompute ----
    // A: 2 x 16B per thread: id = j*256+tid -> qA = id&3, row = id>>2 (g=row>>5, tok=row&31)
    // B: 4 x 16B per thread: id = j*256+tid -> hf, n, spl, gB
    uint32_t adst[2];
    const char* asrc[2];
    #pragma unroll
    for (int j = 0; j < 2; j++) {
        const int id  = j * 256 + tid;
        const int qA  = id & 3;
        const int row = id >> 2;
        const int gA  = row >> 5, tokA = row & 31;
        adst[j] = (uint32_t)(row * A_STRIDE + qA * 16);
        asrc[j] = (const char*)(x + (size_t)(m0 + tokA) * Hdim + gA * 1024 + qA * 4);
    }
    uint32_t bdst[4], bsrc[4];
    #pragma unroll
    for (int j = 0; j < 4; j++) {
        const int id  = j * 256 + tid;
        const int hf  = id & 1;
        const int n   = (id >> 1) & 63;
        const int spl = (id >> 7) & 1;
        const int gB  = (id >> 8) & 3;
        bdst[j] = (uint32_t)(A_BYTES + ((gB * 2 + spl) * 64 + n) * 32 + hf * 16);
        bsrc[j] = (uint32_t)((spl * 262144 + (gB * 64 * 64 + n) * 16 + hf * 8) * 2);
    }
    const char* wbase = (const char*)g_wsplit;

    auto issue = [&](int c, int buf) {
        const uint32_t base = sbase + (uint32_t)buf * BUFB;
        #pragma unroll
        for (int j = 0; j < 2; j++)
            asm volatile("cp.async.cg.shared.global [%0], [%1], 16;"
                         :: "r"(base + adst[j]), "l"(asrc[j] + (size_t)c * 64));
        #pragma unroll
        for (int j = 0; j < 4; j++)
            asm volatile("cp.async.cg.shared.global [%0], [%1], 16;"
                         :: "r"(base + A_BYTES * 0 + bdst[j]),
                            "l"(wbase + bsrc[j] + (size_t)c * 2048));
        asm volatile("cp.async.commit_group;" ::: "memory");
    };

    float acc[8][4];
    #pragma unroll
    for (int nt = 0; nt < 8; nt++)
        #pragma unroll
        for (int q = 0; q < 4; q++) acc[nt][q] = 0.0f;

    const uint32_t arow0 = (uint32_t)((g * 32 + th * 16 + gid) * A_STRIDE + tid4 * 8);
    const uint32_t arow1 = arow0 + 8u * A_STRIDE;
    const uint32_t bwarp = (uint32_t)(A_BYTES + g * 4096 + gid * 32 + tid4 * 8);

    issue(0, 0);

    for (int c = 0; c < NCHUNK; c++) {
        asm volatile("cp.async.wait_group 0;" ::: "memory");
        __syncthreads();
        if (c + 1 < NCHUNK) issue(c + 1, (c + 1) & 1);

        const uint32_t base = sbase + (uint32_t)(c & 1) * BUFB;

        float2 v0, v1, v2, v3;
        asm volatile("ld.shared.v2.f32 {%0,%1},[%2];" : "=f"(v0.x), "=f"(v0.y) : "r"(base + arow0));
        asm volatile("ld.shared.v2.f32 {%0,%1},[%2];" : "=f"(v1.x), "=f"(v1.y) : "r"(base + arow1));
        asm volatile("ld.shared.v2.f32 {%0,%1},[%2];" : "=f"(v2.x), "=f"(v2.y) : "r"(base + arow0 + 32u));
        asm volatile("ld.shared.v2.f32 {%0,%1},[%2];" : "=f"(v3.x), "=f"(v3.y) : "r"(base + arow1 + 32u));

        uint32_t ahi[4], alo[4];
        {
            const float2 vv[4] = {v0, v1, v2, v3};
            #pragma unroll
            for (int i = 0; i < 4; i++) {
                const __half2 h = __float22half2_rn(vv[i]);
                const float2 f = __half22float2(h);
                ahi[i] = h2u(h);
                alo[i] = h2u(__floats2half2_rn(vv[i].x - f.x, vv[i].y - f.y));
            }
        }

        const uint32_t b0a = base + bwarp;
        #pragma unroll
        for (int nt = 0; nt < 8; nt++) {
            uint32_t bh0, bh1, bl0, bl1;
            asm volatile("ld.shared.v2.b32 {%0,%1},[%2];"
                         : "=r"(bh0), "=r"(bh1) : "r"(b0a + (uint32_t)(nt * 256)));
            asm volatile("ld.shared.v2.b32 {%0,%1},[%2];"
                         : "=r"(bl0), "=r"(bl1) : "r"(b0a + (uint32_t)(nt * 256) + 2048u));
            MMAH(acc[nt], ahi[0], ahi[1], ahi[2], ahi[3], bh0, bh1);
            MMAH(acc[nt], ahi[0], ahi[1], ahi[2], ahi[3], bl0, bl1);
            MMAH(acc[nt], alo[0], alo[1], alo[2], alo[3], bh0, bh1);
        }
    }
    __syncthreads();

    // ---- split-K(4) reduction into logits smem [32][68] ----
    #pragma unroll
    for (int gg = 0; gg < 4; gg++) {
        if (g == gg) {
            const int r = th * 16 + gid;
            #pragma unroll
            for (int nt = 0; nt < 8; nt++) {
                const int col = nt * 8 + tid4 * 2;
                if (gg == 0) {
                    smem[r * 68 + col]           = acc[nt][0];
                    smem[r * 68 + col + 1]       = acc[nt][1];
                    smem[(r + 8) * 68 + col]     = acc[nt][2];
                    smem[(r + 8) * 68 + col + 1] = acc[nt][3];
                } else {
                    smem[r * 68 + col]           += acc[nt][0];
                    smem[r * 68 + col + 1]       += acc[nt][1];
                    smem[(r + 8) * 68 + col]     += acc[nt][2];
                    smem[(r + 8) * 68 + col + 1] += acc[nt][3];
                }
            }
        }
        __syncthreads();
    }

    if (tid < MT) {
        const float* row = smem + tid * 68;
        float best1 = -3.4e38f, best2 = -3.4e38f;
        int i1 = 0, i2 = 0;
        #pragma unroll 8
        for (int e = 0; e < Edim; e++) {
            const float l = row[e];
            if (l > best1) { best2 = best1; i2 = i1; best1 = l; i1 = e; }
            else if (l > best2) { best2 = l; i2 = e; }
        }
        float Z = 0.0f;
        #pragma unroll 8
        for (int e = 0; e < Edim; e++) Z += expf(row[e] - best1);
        const float s1 = 1.0f / Z;
        const float s2 = expf(best2 - best1) / Z;
        const float p1 = 1.0f / (1.0f + expf(s2 - s1));
        const float p2 = 1.0f - p1;

        const int m = m0 + tid;
        out[2 * m + 0] = p1;
        out[2 * m + 1] = p2;
        float* oi = out + 2 * T;              // indices stored as float values
        oi[2 * m + 0] = (float)i1;
        oi[2 * m + 1] = (float)i2;
    }
    if (blockIdx.x == 0 && tid == 0) out[4 * T] = 0.0f;
}

extern "C" void kernel_launch(void* const* d_in, const int* in_sizes, int n_in,
                              void* d_out, int out_size)
{
    const float* x = (const float*)d_in[0];
    const float* W = (const float*)d_in[1];
    int T = in_sizes[0] / Hdim;   // 16384
    (void)n_in; (void)out_size;

    static bool attr_done = false;
    if (!attr_done) {
        cudaFuncSetAttribute(moe_gate_v11_kernel,
                             cudaFuncAttributeMaxDynamicSharedMemorySize, SMEM_BYTES);
        attr_done = true;
    }
    split_w_kernel<<<1024, 256>>>(W);
    moe_gate_v11_kernel<<<T / MT, 256, SMEM_BYTES>>>(x, (float*)d_out, T);
}